// round 8
// baseline (speedup 1.0000x reference)
#include <cuda_runtime.h>
#include <math.h>
#include <stdint.h>

#define E_DIM   1024
#define S_LEN   2048
#define N_BATCH 2
#define N_HEADS 16
#define H_DIM   64
#define M_ROWS  (N_BATCH * S_LEN)   // 4096

// Scratch (allocation-free). g_v holds V^T in [b*16+h][d][s] layout (written by the
// V-projection epilogue); g_q/g_k normal [token][h*64+d]; g_o attention output.
__device__ float g_q[(size_t)M_ROWS * E_DIM];
__device__ float g_k[(size_t)M_ROWS * E_DIM];
__device__ float g_v[(size_t)M_ROWS * E_DIM];
__device__ float g_o[(size_t)M_ROWS * E_DIM];

// ===================== helpers =====================
__device__ __forceinline__ uint32_t smem_u32(const void* p) {
    uint32_t a;
    asm("{ .reg .u64 t; cvta.to.shared.u64 t, %1; cvt.u32.u64 %0, t; }" : "=r"(a) : "l"(p));
    return a;
}
__device__ __forceinline__ uint32_t cvt_tf32(float f) {
    uint32_t u;
    asm("cvt.rna.tf32.f32 %0, %1;" : "=r"(u) : "f"(f));
    return u;
}
__device__ __forceinline__ void split2(uint32_t r, uint32_t& hi, uint32_t& lo) {
    float f = __uint_as_float(r);
    hi = cvt_tf32(f);
    lo = cvt_tf32(f - __uint_as_float(hi));
}
__device__ __forceinline__ void split4(float4 v, uint4& hi, uint4& lo) {
    hi.x = cvt_tf32(v.x); lo.x = cvt_tf32(v.x - __uint_as_float(hi.x));
    hi.y = cvt_tf32(v.y); lo.y = cvt_tf32(v.y - __uint_as_float(hi.y));
    hi.z = cvt_tf32(v.z); lo.z = cvt_tf32(v.z - __uint_as_float(hi.z));
    hi.w = cvt_tf32(v.w); lo.w = cvt_tf32(v.w - __uint_as_float(hi.w));
}

#define CP16(dst, src) \
    asm volatile("cp.async.cg.shared.global [%0], [%1], 16;" :: "r"(dst), "l"(src))
#define CPCOMMIT() asm volatile("cp.async.commit_group;" ::: "memory")
#define CPWAIT0()  asm volatile("cp.async.wait_group 0;" ::: "memory")

#define LDSM_X4(r0, r1, r2, r3, addr)                                          \
    asm volatile("ldmatrix.sync.aligned.m8n8.x4.shared.b16 {%0,%1,%2,%3}, [%4];" \
                 : "=r"(r0), "=r"(r1), "=r"(r2), "=r"(r3) : "r"(addr))
#define LDSM_X2(r0, r1, addr)                                                  \
    asm volatile("ldmatrix.sync.aligned.m8n8.x2.shared.b16 {%0,%1}, [%2];"     \
                 : "=r"(r0), "=r"(r1) : "r"(addr))

#define MMA_TF32(d, A, b0v, b1v)                                               \
    asm volatile("mma.sync.aligned.m16n8k8.row.col.f32.tf32.tf32.f32 "         \
                 "{%0,%1,%2,%3}, {%4,%5,%6,%7}, {%8,%9}, {%0,%1,%2,%3};"       \
                 : "+f"((d)[0]), "+f"((d)[1]), "+f"((d)[2]), "+f"((d)[3])      \
                 : "r"((A)[0]), "r"((A)[1]), "r"((A)[2]), "r"((A)[3]),         \
                   "r"(b0v), "r"(b1v))

#define STS64(addr, v0, v1) \
    asm volatile("st.shared.v2.f32 [%0], {%1,%2};" :: "r"(addr), "f"(v0), "f"(v1))
#define STS128U(addr, v) \
    asm volatile("st.shared.v4.b32 [%0], {%1,%2,%3,%4};"                       \
                 :: "r"(addr), "r"((v).x), "r"((v).y), "r"((v).z), "r"((v).w))

// ===================== mma.sync TF32-split GEMM: Y = X @ W^T + b =====================
// CTA 128x128, 8 warps (2m x 4n), warp tile 64x32. K chunk 16.
// PRODUCER-SIDE hi/lo split: LDG raw fp32 -> split once -> STS into Ahi/Alo/Bhi/Blo.
// Consumer hot loop is pure LDSM + MMA (zero ALU). 2-stage smem, LDG register prefetch.
// 80B row stride keeps ldmatrix conflict-free.
#define NCHUNK   (E_DIM / 16)         // 64
#define ROWB     80
#define MATB     (128 * ROWB)         // 10240 per hi/lo half-tile
#define AHI_OFF  0u
#define ALO_OFF  10240u
#define BHI_OFF  20480u
#define BLO_OFF  30720u
#define STAGE_B  40960u
#define GEMM_SMEM (2 * 40960)         // 81920

__global__ __launch_bounds__(256) void gemm_tc_kernel(
    const float* __restrict__ X0, const float* __restrict__ X1, const float* __restrict__ X2,
    const float* __restrict__ W0, const float* __restrict__ W1, const float* __restrict__ W2,
    const float* __restrict__ B0, const float* __restrict__ B1, const float* __restrict__ B2,
    float* __restrict__ Y0, float* __restrict__ Y1, float* __restrict__ Y2,
    float* __restrict__ YT)
{
    extern __shared__ char smem[];
    const int z = blockIdx.z;
    const float* __restrict__ X  = (z == 0) ? X0 : ((z == 1) ? X1 : X2);
    const float* __restrict__ W  = (z == 0) ? W0 : ((z == 1) ? W1 : W2);
    const float* __restrict__ Bv = (z == 0) ? B0 : ((z == 1) ? B1 : B2);
    float* __restrict__ Y        = (z == 0) ? Y0 : ((z == 1) ? Y1 : Y2);

    const int tid  = threadIdx.x;
    const int lane = tid & 31;
    const int wid  = tid >> 5;
    const int wm   = wid >> 2;
    const int wn   = wid & 3;
    const int m0 = blockIdx.y * 128;
    const int n0 = blockIdx.x * 128;

    const uint32_t sb = smem_u32(smem);

    // producer addressing: thread covers rows prow, prow+64 of both X and W tiles
    const int prow = tid >> 2;        // 0..63
    const int pc4  = tid & 3;         // 16B slot within 16-float row
    const float* Xsrc = &X[(size_t)(m0 + prow) * E_DIM + pc4 * 4];
    const float* Wsrc = &W[(size_t)(n0 + prow) * E_DIM + pc4 * 4];
    const uint32_t d0 = sb + (uint32_t)prow * ROWB + (uint32_t)pc4 * 16;
    const uint32_t d1 = d0 + 64 * ROWB;

    float4 xr0, xr1, wr0, wr1;        // raw prefetch registers

    #define LDG_CHUNK(c) do {                                                  \
        xr0 = *(const float4*)(Xsrc + (c) * 16);                               \
        xr1 = *(const float4*)(Xsrc + (size_t)64 * E_DIM + (c) * 16);          \
        wr0 = *(const float4*)(Wsrc + (c) * 16);                               \
        wr1 = *(const float4*)(Wsrc + (size_t)64 * E_DIM + (c) * 16);          \
    } while (0)

    #define STS_CHUNK(st) do {                                                 \
        uint4 h_, l_;                                                          \
        uint32_t s_ = (uint32_t)(st) * STAGE_B;                                \
        split4(xr0, h_, l_);                                                   \
        STS128U(d0 + s_ + AHI_OFF, h_); STS128U(d0 + s_ + ALO_OFF, l_);        \
        split4(xr1, h_, l_);                                                   \
        STS128U(d1 + s_ + AHI_OFF, h_); STS128U(d1 + s_ + ALO_OFF, l_);        \
        split4(wr0, h_, l_);                                                   \
        STS128U(d0 + s_ + BHI_OFF, h_); STS128U(d0 + s_ + BLO_OFF, l_);        \
        split4(wr1, h_, l_);                                                   \
        STS128U(d1 + s_ + BHI_OFF, h_); STS128U(d1 + s_ + BLO_OFF, l_);        \
    } while (0)

    // consumer ldmatrix addressing
    const int i4 = lane >> 3, r8 = lane & 7;
    const uint32_t a_off = (uint32_t)(wm * 64 + ((i4 & 1) << 3) + r8) * ROWB
                         + (uint32_t)((i4 >> 1) << 4);
    const uint32_t b_off = (uint32_t)(wn * 32 + r8) * ROWB
                         + (uint32_t)((i4 & 1) << 4);

    float acc[4][4][4];
#pragma unroll
    for (int mt = 0; mt < 4; ++mt)
#pragma unroll
        for (int nt = 0; nt < 4; ++nt)
#pragma unroll
            for (int r = 0; r < 4; ++r) acc[mt][nt][r] = 0.f;

    // prologue
    LDG_CHUNK(0);
    STS_CHUNK(0);
    LDG_CHUNK(1);
    __syncthreads();

    for (int c = 0; c < NCHUNK; ++c) {
        const uint32_t stb = sb + (uint32_t)(c & 1) * STAGE_B;

#pragma unroll
        for (int ks = 0; ks < 2; ++ks) {
            uint32_t bh[4][2], bl[4][2];
#pragma unroll
            for (int nt = 0; nt < 4; ++nt) {
                const uint32_t ba = stb + b_off + nt * (8 * ROWB) + ks * 32;
                LDSM_X2(bh[nt][0], bh[nt][1], ba + BHI_OFF);
                LDSM_X2(bl[nt][0], bl[nt][1], ba + BLO_OFF);
            }
#pragma unroll
            for (int mt = 0; mt < 4; ++mt) {
                const uint32_t aa = stb + a_off + mt * (16 * ROWB) + ks * 32;
                uint32_t ah[4], al[4];
                LDSM_X4(ah[0], ah[1], ah[2], ah[3], aa + AHI_OFF);
                LDSM_X4(al[0], al[1], al[2], al[3], aa + ALO_OFF);
#pragma unroll
                for (int nt = 0; nt < 4; ++nt) {
                    MMA_TF32(acc[mt][nt], ah, bl[nt][0], bl[nt][1]);
                    MMA_TF32(acc[mt][nt], al, bh[nt][0], bh[nt][1]);
                    MMA_TF32(acc[mt][nt], ah, bh[nt][0], bh[nt][1]);
                }
            }
        }

        if (c + 1 < NCHUNK) {
            STS_CHUNK((c + 1) & 1);          // writes stage !(c&1): safe, see hazard note
            if (c + 2 < NCHUNK) LDG_CHUNK(c + 2);
        }
        __syncthreads();
    }

    if (z == 2) {
        // V^T epilogue: YT[(b*16+h)*64 + d][s] = acc + bias
        const int bq = m0 >> 11;
#pragma unroll
        for (int nt = 0; nt < 4; ++nt) {
            const int col = n0 + wn * 32 + nt * 8 + 2 * (lane & 3);
            const int hh = col >> 6, dd = col & 63;
            const float bx = __ldg(&Bv[col]);
            const float by = __ldg(&Bv[col + 1]);
            float* base0 = &YT[((size_t)(bq * 16 + hh) * 64 + dd) * S_LEN];
            float* base1 = base0 + S_LEN;
#pragma unroll
            for (int mt = 0; mt < 4; ++mt) {
                const int s = (m0 & 2047) + wm * 64 + mt * 16 + (lane >> 2);
                base0[s]     = acc[mt][nt][0] + bx;
                base1[s]     = acc[mt][nt][1] + by;
                base0[s + 8] = acc[mt][nt][2] + bx;
                base1[s + 8] = acc[mt][nt][3] + by;
            }
        }
    } else {
#pragma unroll
        for (int nt = 0; nt < 4; ++nt) {
            const int col = n0 + wn * 32 + nt * 8 + 2 * (lane & 3);
            const float bx = __ldg(&Bv[col]);
            const float by = __ldg(&Bv[col + 1]);
#pragma unroll
            for (int mt = 0; mt < 4; ++mt) {
                const int r0i = m0 + wm * 64 + mt * 16 + (lane >> 2);
                float2 v0 = make_float2(acc[mt][nt][0] + bx, acc[mt][nt][1] + by);
                float2 v1 = make_float2(acc[mt][nt][2] + bx, acc[mt][nt][3] + by);
                *(float2*)&Y[(size_t)r0i * E_DIM + col] = v0;
                *(float2*)&Y[(size_t)(r0i + 8) * E_DIM + col] = v1;
            }
        }
    }
}

// ===================== Tensorized causal flash attention (unchanged from R7) =====================
#define AQ_OFF   0u
#define AK_OFF   16384u
#define AV_OFF   32768u
#define AST_B    32768u
#define AP_OFF   81920u
#define ATTN_SMEM 98304

__global__ __launch_bounds__(128) void attn_tc_kernel(
    const float* __restrict__ Qp, const float* __restrict__ Kp,
    const float* __restrict__ VTp, float* __restrict__ Op)
{
    extern __shared__ char smem[];
    const uint32_t sb = smem_u32(smem);
    const int tid = threadIdx.x, lane = tid & 31, w = tid >> 5;
    const int i = blockIdx.x, bh = blockIdx.y;
    const int b = bh >> 4, h = bh & 15;

    const size_t qbase  = ((size_t)b * S_LEN + i * 64) * E_DIM + h * 64;
    const size_t kbase  = (size_t)b * S_LEN * E_DIM + h * 64;
    const size_t vtbase = (size_t)bh * 64 * S_LEN;

#pragma unroll
    for (int l = 0; l < 8; ++l) {
        int idx = tid + l * 128, row = idx >> 4, sl = idx & 15;
        CP16(sb + AQ_OFF + row * 256 + (((sl) ^ (row & 7)) << 4),
             Qp + qbase + (size_t)row * E_DIM + sl * 4);
    }

    #define ISSUE_KV(j_, st_) do {                                             \
        _Pragma("unroll")                                                      \
        for (int l = 0; l < 8; ++l) {                                          \
            int idx_ = tid + l * 128, row_ = idx_ >> 4, sl_ = idx_ & 15;       \
            uint32_t sw_ = (uint32_t)(row_ * 256 + (((sl_) ^ (row_ & 7)) << 4)); \
            CP16(sb + AK_OFF + (uint32_t)(st_) * AST_B + sw_,                  \
                 Kp + kbase + (size_t)((j_) * 64 + row_) * E_DIM + sl_ * 4);   \
            CP16(sb + AV_OFF + (uint32_t)(st_) * AST_B + sw_,                  \
                 VTp + vtbase + (size_t)row_ * S_LEN + (j_) * 64 + sl_ * 4);   \
        }                                                                      \
    } while (0)

    ISSUE_KV(0, 0);
    CPCOMMIT();

    const int i4 = lane >> 3, r8 = lane & 7;
    const int lr = lane >> 2;
    const int lc0 = 2 * (lane & 3);
    const int qrow = w * 16 + ((i4 & 1) << 3) + r8;
    const uint32_t qrb = sb + AQ_OFF + qrow * 256;
    const int qrm = qrow & 7;
    const int prow = ((i4 & 1) << 3) + r8;
    const uint32_t prb = sb + AP_OFF + (uint32_t)w * 4096 + prow * 256;
    const int prm = prow & 7;
    const uint32_t pw = sb + AP_OFF + (uint32_t)w * 4096;
    const int lrow0 = w * 16 + lr;

    float m_prev0 = -INFINITY, m_prev1 = -INFINITY;
    float lsum0 = 0.f, lsum1 = 0.f;
    float o[8][4];
#pragma unroll
    for (int nt = 0; nt < 8; ++nt)
#pragma unroll
        for (int r = 0; r < 4; ++r) o[nt][r] = 0.f;

    for (int j = 0; j <= i; ++j) {
        CPWAIT0();
        __syncthreads();
        if (j < i) ISSUE_KV(j + 1, (j + 1) & 1);
        CPCOMMIT();

        const uint32_t kb  = sb + AK_OFF + (uint32_t)(j & 1) * AST_B;
        const uint32_t vtb = sb + AV_OFF + (uint32_t)(j & 1) * AST_B;

        float sacc[8][4];
#pragma unroll
        for (int nt = 0; nt < 8; ++nt)
#pragma unroll
            for (int r = 0; r < 4; ++r) sacc[nt][r] = 0.f;

#pragma unroll
        for (int ks = 0; ks < 8; ++ks) {
            uint32_t a0, a1, a2, a3;
            LDSM_X4(a0, a1, a2, a3, qrb + ((((ks << 1) | (i4 >> 1)) ^ qrm) << 4));
            uint32_t ah[4], al[4];
            split2(a0, ah[0], al[0]); split2(a1, ah[1], al[1]);
            split2(a2, ah[2], al[2]); split2(a3, ah[3], al[3]);
#pragma unroll
            for (int nt = 0; nt < 8; ++nt) {
                const int brow = (nt << 3) | r8;
                uint32_t b0, b1;
                LDSM_X2(b0, b1, kb + brow * 256 + ((((ks << 1) | (i4 & 1)) ^ (brow & 7)) << 4));
                uint32_t bh0, bl0, bh1, bl1;
                split2(b0, bh0, bl0); split2(b1, bh1, bl1);
                MMA_TF32(sacc[nt], ah, bl0, bl1);
                MMA_TF32(sacc[nt], al, bh0, bh1);
                MMA_TF32(sacc[nt], ah, bh0, bh1);
            }
        }

        const bool diag = (j == i);
        float mloc0 = -INFINITY, mloc1 = -INFINITY;
#pragma unroll
        for (int nt = 0; nt < 8; ++nt) {
            const int c0 = (nt << 3) + lc0;
            float s0 = sacc[nt][0] * 0.125f, s1 = sacc[nt][1] * 0.125f;
            float s2 = sacc[nt][2] * 0.125f, s3 = sacc[nt][3] * 0.125f;
            if (diag) {
                if (c0     > lrow0)     s0 = -INFINITY;
                if (c0 + 1 > lrow0)     s1 = -INFINITY;
                if (c0     > lrow0 + 8) s2 = -INFINITY;
                if (c0 + 1 > lrow0 + 8) s3 = -INFINITY;
            }
            sacc[nt][0] = s0; sacc[nt][1] = s1; sacc[nt][2] = s2; sacc[nt][3] = s3;
            mloc0 = fmaxf(mloc0, fmaxf(s0, s1));
            mloc1 = fmaxf(mloc1, fmaxf(s2, s3));
        }
        mloc0 = fmaxf(mloc0, __shfl_xor_sync(0xffffffffu, mloc0, 1));
        mloc0 = fmaxf(mloc0, __shfl_xor_sync(0xffffffffu, mloc0, 2));
        mloc1 = fmaxf(mloc1, __shfl_xor_sync(0xffffffffu, mloc1, 1));
        mloc1 = fmaxf(mloc1, __shfl_xor_sync(0xffffffffu, mloc1, 2));

        const float m_new0 = fmaxf(m_prev0, mloc0);
        const float m_new1 = fmaxf(m_prev1, mloc1);
        const float fac0 = (m_prev0 == -INFINITY) ? 0.f : __expf(m_prev0 - m_new0);
        const float fac1 = (m_prev1 == -INFINITY) ? 0.f : __expf(m_prev1 - m_new1);
        m_prev0 = m_new0; m_prev1 = m_new1;

        float ls0 = 0.f, ls1 = 0.f;
        const int pslot_lo = (lane & 3) >> 1;
        const uint32_t pword = (uint32_t)((lane & 1) << 3);
#pragma unroll
        for (int nt = 0; nt < 8; ++nt) {
            float p0 = __expf(sacc[nt][0] - m_new0);
            float p1 = __expf(sacc[nt][1] - m_new0);
            float p2 = __expf(sacc[nt][2] - m_new1);
            float p3 = __expf(sacc[nt][3] - m_new1);
            ls0 += p0 + p1;
            ls1 += p2 + p3;
            const int slot = (nt << 1) | pslot_lo;
            STS64(pw + lr * 256 + ((slot ^ (lr & 7)) << 4) + pword, p0, p1);
            STS64(pw + (lr + 8) * 256 + ((slot ^ ((lr + 8) & 7)) << 4) + pword, p2, p3);
        }
        ls0 += __shfl_xor_sync(0xffffffffu, ls0, 1);
        ls0 += __shfl_xor_sync(0xffffffffu, ls0, 2);
        ls1 += __shfl_xor_sync(0xffffffffu, ls1, 1);
        ls1 += __shfl_xor_sync(0xffffffffu, ls1, 2);
        lsum0 = lsum0 * fac0 + ls0;
        lsum1 = lsum1 * fac1 + ls1;

#pragma unroll
        for (int nt = 0; nt < 8; ++nt) {
            o[nt][0] *= fac0; o[nt][1] *= fac0;
            o[nt][2] *= fac1; o[nt][3] *= fac1;
        }
        __syncwarp();

#pragma unroll
        for (int ks = 0; ks < 8; ++ks) {
            uint32_t a0, a1, a2, a3;
            LDSM_X4(a0, a1, a2, a3, prb + ((((ks << 1) | (i4 >> 1)) ^ prm) << 4));
            uint32_t ah[4], al[4];
            split2(a0, ah[0], al[0]); split2(a1, ah[1], al[1]);
            split2(a2, ah[2], al[2]); split2(a3, ah[3], al[3]);
#pragma unroll
            for (int nt = 0; nt < 8; ++nt) {
                const int vrow = (nt << 3) | r8;
                uint32_t b0, b1;
                LDSM_X2(b0, b1, vtb + vrow * 256 + ((((ks << 1) | (i4 & 1)) ^ (vrow & 7)) << 4));
                uint32_t bh0, bl0, bh1, bl1;
                split2(b0, bh0, bl0); split2(b1, bh1, bl1);
                MMA_TF32(o[nt], ah, bl0, bl1);
                MMA_TF32(o[nt], al, bh0, bh1);
                MMA_TF32(o[nt], ah, bh0, bh1);
            }
        }
        __syncwarp();
    }

    const float inv0 = 1.f / lsum0;
    const float inv1 = 1.f / lsum1;
    const size_t orow = (size_t)b * S_LEN + i * 64 + w * 16 + lr;
#pragma unroll
    for (int nt = 0; nt < 8; ++nt) {
        const int col = h * 64 + (nt << 3) + lc0;
        float2 v0 = make_float2(o[nt][0] * inv0, o[nt][1] * inv0);
        float2 v1 = make_float2(o[nt][2] * inv1, o[nt][3] * inv1);
        *(float2*)&Op[orow * E_DIM + col] = v0;
        *(float2*)&Op[(orow + 8) * E_DIM + col] = v1;
    }
}

// ===================== launch =====================
extern "C" void kernel_launch(void* const* d_in, const int* in_sizes, int n_in,
                              void* d_out, int out_size)
{
    (void)in_sizes; (void)n_in; (void)out_size;
    const float* q  = (const float*)d_in[0];
    const float* k  = (const float*)d_in[1];
    const float* v  = (const float*)d_in[2];
    const float* Wq = (const float*)d_in[3];
    const float* bq = (const float*)d_in[4];
    const float* Wk = (const float*)d_in[5];
    const float* bk = (const float*)d_in[6];
    const float* Wv = (const float*)d_in[7];
    const float* bv = (const float*)d_in[8];
    const float* Wo = (const float*)d_in[9];
    const float* bo = (const float*)d_in[10];
    float* out = (float*)d_out;

    float *gq, *gk, *gv, *go;
    cudaGetSymbolAddress((void**)&gq, g_q);
    cudaGetSymbolAddress((void**)&gk, g_k);
    cudaGetSymbolAddress((void**)&gv, g_v);
    cudaGetSymbolAddress((void**)&go, g_o);

    cudaFuncSetAttribute(gemm_tc_kernel, cudaFuncAttributeMaxDynamicSharedMemorySize, GEMM_SMEM);
    cudaFuncSetAttribute(attn_tc_kernel, cudaFuncAttributeMaxDynamicSharedMemorySize, ATTN_SMEM);

    // Q/K/V projections; z==2 (V) writes V^T [bh][d][s] into gv.
    dim3 gridP(E_DIM / 128, M_ROWS / 128, 3);
    gemm_tc_kernel<<<gridP, 256, GEMM_SMEM>>>(q, k, v, Wq, Wk, Wv, bq, bk, bv,
                                              gq, gk, gv, gv);

    // Tensorized causal flash attention.
    dim3 gridA(S_LEN / 64, N_BATCH * N_HEADS);
    attn_tc_kernel<<<gridA, 128, ATTN_SMEM>>>(gq, gk, gv, go);

    // Output projection into d_out.
    dim3 gridO(E_DIM / 128, M_ROWS / 128, 1);
    gemm_tc_kernel<<<gridO, 256, GEMM_SMEM>>>(go, go, go, Wo, Wo, Wo, bo, bo, bo,
                                              out, out, out, nullptr);
}

// round 9
// speedup vs baseline: 1.1072x; 1.1072x over previous
#include <cuda_runtime.h>
#include <math.h>
#include <stdint.h>

#define E_DIM   1024
#define S_LEN   2048
#define N_BATCH 2
#define N_HEADS 16
#define H_DIM   64
#define M_ROWS  (N_BATCH * S_LEN)   // 4096
#define ME      ((size_t)M_ROWS * E_DIM)   // 4M elems
#define EE      ((size_t)E_DIM * E_DIM)    // 1M elems

// ---------- global scratch (allocation-free) ----------
// pre-split GEMM inputs
__device__ uint32_t s_xq_hi[ME], s_xq_lo[ME];
__device__ uint32_t s_xk_hi[ME], s_xk_lo[ME];
__device__ uint32_t s_xv_hi[ME], s_xv_lo[ME];
__device__ uint32_t s_wq_hi[EE], s_wq_lo[EE];
__device__ uint32_t s_wk_hi[EE], s_wk_lo[EE];
__device__ uint32_t s_wv_hi[EE], s_wv_lo[EE];
__device__ uint32_t s_wo_hi[EE], s_wo_lo[EE];
// projected, pre-split attention operands
__device__ uint32_t s_q_hi[ME], s_q_lo[ME];
__device__ uint32_t s_k_hi[ME], s_k_lo[ME];
__device__ uint32_t s_vt_hi[ME], s_vt_lo[ME];   // [bh][d][s]
// attention output, pre-split for out-proj
__device__ uint32_t s_o_hi[ME], s_o_lo[ME];

// ===================== helpers =====================
__device__ __forceinline__ uint32_t smem_u32(const void* p) {
    uint32_t a;
    asm("{ .reg .u64 t; cvta.to.shared.u64 t, %1; cvt.u32.u64 %0, t; }" : "=r"(a) : "l"(p));
    return a;
}
__device__ __forceinline__ uint32_t cvt_tf32(float f) {
    uint32_t u;
    asm("cvt.rna.tf32.f32 %0, %1;" : "=r"(u) : "f"(f));
    return u;
}
__device__ __forceinline__ void split2(float f, uint32_t& hi, uint32_t& lo) {
    hi = cvt_tf32(f);
    lo = cvt_tf32(f - __uint_as_float(hi));
}
__device__ __forceinline__ void split4(float4 v, uint4& hi, uint4& lo) {
    split2(v.x, hi.x, lo.x);
    split2(v.y, hi.y, lo.y);
    split2(v.z, hi.z, lo.z);
    split2(v.w, hi.w, lo.w);
}

#define CP16(dst, src) \
    asm volatile("cp.async.cg.shared.global [%0], [%1], 16;" :: "r"(dst), "l"(src))
#define CPCOMMIT() asm volatile("cp.async.commit_group;" ::: "memory")
#define CPWAIT1()  asm volatile("cp.async.wait_group 1;" ::: "memory")
#define CPWAIT0()  asm volatile("cp.async.wait_group 0;" ::: "memory")

#define LDSM_X4(r0, r1, r2, r3, addr)                                          \
    asm volatile("ldmatrix.sync.aligned.m8n8.x4.shared.b16 {%0,%1,%2,%3}, [%4];" \
                 : "=r"(r0), "=r"(r1), "=r"(r2), "=r"(r3) : "r"(addr))
#define LDSM_X2(r0, r1, addr)                                                  \
    asm volatile("ldmatrix.sync.aligned.m8n8.x2.shared.b16 {%0,%1}, [%2];"     \
                 : "=r"(r0), "=r"(r1) : "r"(addr))

#define MMA_TF32(d, A, b0v, b1v)                                               \
    asm volatile("mma.sync.aligned.m16n8k8.row.col.f32.tf32.tf32.f32 "         \
                 "{%0,%1,%2,%3}, {%4,%5,%6,%7}, {%8,%9}, {%0,%1,%2,%3};"       \
                 : "+f"((d)[0]), "+f"((d)[1]), "+f"((d)[2]), "+f"((d)[3])      \
                 : "r"((A)[0]), "r"((A)[1]), "r"((A)[2]), "r"((A)[3]),         \
                   "r"(b0v), "r"(b1v))

#define STS64(addr, v0, v1) \
    asm volatile("st.shared.v2.f32 [%0], {%1,%2};" :: "r"(addr), "f"(v0), "f"(v1))
#define BARP(id) asm volatile("bar.sync %0, 64;" :: "r"(id) : "memory")

// ===================== pre-split kernel =====================
__global__ __launch_bounds__(256) void split_kernel(
    const float4* __restrict__ src, uint4* __restrict__ hi, uint4* __restrict__ lo, int n4)
{
    int i = blockIdx.x * blockDim.x + threadIdx.x;
    if (i < n4) {
        uint4 h, l;
        split4(src[i], h, l);
        hi[i] = h;
        lo[i] = l;
    }
}

// ===================== GEMM: Y = X @ W^T + b (pre-split operands) =====================
// CTA 128x128, 8 warps (2m x 4n), K chunk 16, 2-stage cp.async of 4 hi/lo tiles.
// Hot loop: pure LDSM + MMA. Rows 16 floats @ 80B stride (conflict-free ldmatrix).
#define NCHUNK   (E_DIM / 16)
#define ROWB     80
#define AHI_OFF  0u
#define ALO_OFF  10240u
#define BHI_OFF  20480u
#define BLO_OFF  30720u
#define STAGE_B  40960u
#define GEMM_SMEM (2 * 40960)

__global__ __launch_bounds__(256, 2) void gemm_tc_kernel(
    const float* __restrict__ bq, const float* __restrict__ bk,
    const float* __restrict__ bv, const float* __restrict__ bo,
    float* __restrict__ out, int is_out)
{
    extern __shared__ char smem[];
    const int z = blockIdx.z;
    const uint32_t *Xhi, *Xlo, *Whi, *Wlo;
    const float* Bv;
    int mode;
    if (is_out) { Xhi = s_o_hi;  Xlo = s_o_lo;  Whi = s_wo_hi; Wlo = s_wo_lo; Bv = bo; mode = 3; }
    else if (z == 0) { Xhi = s_xq_hi; Xlo = s_xq_lo; Whi = s_wq_hi; Wlo = s_wq_lo; Bv = bq; mode = 0; }
    else if (z == 1) { Xhi = s_xk_hi; Xlo = s_xk_lo; Whi = s_wk_hi; Wlo = s_wk_lo; Bv = bk; mode = 1; }
    else             { Xhi = s_xv_hi; Xlo = s_xv_lo; Whi = s_wv_hi; Wlo = s_wv_lo; Bv = bv; mode = 2; }

    const int tid  = threadIdx.x;
    const int lane = tid & 31;
    const int wid  = tid >> 5;
    const int wm   = wid >> 2;
    const int wn   = wid & 3;
    const int m0 = blockIdx.y * 128;
    const int n0 = blockIdx.x * 128;

    const uint32_t sb = smem_u32(smem);

    const int prow = tid >> 2;        // 0..63 (and +64)
    const int pc4  = tid & 3;
    const size_t xoff = (size_t)(m0 + prow) * E_DIM + pc4 * 4;
    const size_t woff = (size_t)(n0 + prow) * E_DIM + pc4 * 4;
    const uint32_t pd = (uint32_t)prow * ROWB + (uint32_t)pc4 * 16;

    #define GCP_CHUNK(c, st) do {                                              \
        uint32_t base_ = sb + (uint32_t)(st) * STAGE_B + pd;                   \
        size_t ko_ = (size_t)(c) * 16;                                         \
        _Pragma("unroll")                                                      \
        for (int r = 0; r < 2; ++r) {                                          \
            size_t sx_ = xoff + (size_t)r * 64 * E_DIM + ko_;                  \
            size_t sw_ = woff + (size_t)r * 64 * E_DIM + ko_;                  \
            uint32_t dd_ = base_ + (uint32_t)r * 5120;                         \
            CP16(dd_ + AHI_OFF, Xhi + sx_);                                    \
            CP16(dd_ + ALO_OFF, Xlo + sx_);                                    \
            CP16(dd_ + BHI_OFF, Whi + sw_);                                    \
            CP16(dd_ + BLO_OFF, Wlo + sw_);                                    \
        }                                                                      \
    } while (0)

    GCP_CHUNK(0, 0); CPCOMMIT();
    GCP_CHUNK(1, 1); CPCOMMIT();

    const int i4 = lane >> 3, r8 = lane & 7;
    const uint32_t a_off = (uint32_t)(wm * 64 + ((i4 & 1) << 3) + r8) * ROWB
                         + (uint32_t)((i4 >> 1) << 4);
    const uint32_t b_off = (uint32_t)(wn * 32 + r8) * ROWB
                         + (uint32_t)((i4 & 1) << 4);

    float acc[4][4][4];
#pragma unroll
    for (int mt = 0; mt < 4; ++mt)
#pragma unroll
        for (int nt = 0; nt < 4; ++nt)
#pragma unroll
            for (int r = 0; r < 4; ++r) acc[mt][nt][r] = 0.f;

    for (int c = 0; c < NCHUNK; ++c) {
        CPWAIT1();
        __syncthreads();
        const uint32_t stb = sb + (uint32_t)(c & 1) * STAGE_B;

#pragma unroll
        for (int ks = 0; ks < 2; ++ks) {
            uint32_t bhv[4][2], blv[4][2];
#pragma unroll
            for (int nt = 0; nt < 4; ++nt) {
                const uint32_t ba = stb + b_off + nt * (8 * ROWB) + ks * 32;
                LDSM_X2(bhv[nt][0], bhv[nt][1], ba + BHI_OFF);
                LDSM_X2(blv[nt][0], blv[nt][1], ba + BLO_OFF);
            }
#pragma unroll
            for (int mt = 0; mt < 4; ++mt) {
                const uint32_t aa = stb + a_off + mt * (16 * ROWB) + ks * 32;
                uint32_t ah[4], al[4];
                LDSM_X4(ah[0], ah[1], ah[2], ah[3], aa + AHI_OFF);
                LDSM_X4(al[0], al[1], al[2], al[3], aa + ALO_OFF);
#pragma unroll
                for (int nt = 0; nt < 4; ++nt) {
                    MMA_TF32(acc[mt][nt], ah, blv[nt][0], blv[nt][1]);
                    MMA_TF32(acc[mt][nt], al, bhv[nt][0], bhv[nt][1]);
                    MMA_TF32(acc[mt][nt], ah, bhv[nt][0], bhv[nt][1]);
                }
            }
        }

        __syncthreads();
        if (c + 2 < NCHUNK) GCP_CHUNK(c + 2, c & 1);
        CPCOMMIT();
    }

    // ---- epilogue ----
    if (mode == 3) {
#pragma unroll
        for (int nt = 0; nt < 4; ++nt) {
            const int col = n0 + wn * 32 + nt * 8 + 2 * (lane & 3);
            const float bx = __ldg(&Bv[col]);
            const float by = __ldg(&Bv[col + 1]);
#pragma unroll
            for (int mt = 0; mt < 4; ++mt) {
                const int r0i = m0 + wm * 64 + mt * 16 + (lane >> 2);
                *(float2*)&out[(size_t)r0i * E_DIM + col] =
                    make_float2(acc[mt][nt][0] + bx, acc[mt][nt][1] + by);
                *(float2*)&out[(size_t)(r0i + 8) * E_DIM + col] =
                    make_float2(acc[mt][nt][2] + bx, acc[mt][nt][3] + by);
            }
        }
    } else if (mode == 2) {
        // V^T split epilogue: s_vt_{hi,lo}[(b*16+h)*64 + d][s]
        const int bq2 = m0 >> 11;
#pragma unroll
        for (int nt = 0; nt < 4; ++nt) {
            const int col = n0 + wn * 32 + nt * 8 + 2 * (lane & 3);
            const int hh = col >> 6, dd = col & 63;
            const float bx = __ldg(&Bv[col]);
            const float by = __ldg(&Bv[col + 1]);
            const size_t b0i = ((size_t)(bq2 * 16 + hh) * 64 + dd) * S_LEN;
            const size_t b1i = b0i + S_LEN;
#pragma unroll
            for (int mt = 0; mt < 4; ++mt) {
                const int s = (m0 & 2047) + wm * 64 + mt * 16 + (lane >> 2);
                uint32_t h0, l0, h1, l1;
                split2(acc[mt][nt][0] + bx, h0, l0);
                split2(acc[mt][nt][1] + by, h1, l1);
                s_vt_hi[b0i + s] = h0; s_vt_lo[b0i + s] = l0;
                s_vt_hi[b1i + s] = h1; s_vt_lo[b1i + s] = l1;
                split2(acc[mt][nt][2] + bx, h0, l0);
                split2(acc[mt][nt][3] + by, h1, l1);
                s_vt_hi[b0i + s + 8] = h0; s_vt_lo[b0i + s + 8] = l0;
                s_vt_hi[b1i + s + 8] = h1; s_vt_lo[b1i + s + 8] = l1;
            }
        }
    } else {
        uint32_t* Yh = (mode == 0) ? s_q_hi : s_k_hi;
        uint32_t* Yl = (mode == 0) ? s_q_lo : s_k_lo;
#pragma unroll
        for (int nt = 0; nt < 4; ++nt) {
            const int col = n0 + wn * 32 + nt * 8 + 2 * (lane & 3);
            const float bx = __ldg(&Bv[col]);
            const float by = __ldg(&Bv[col + 1]);
#pragma unroll
            for (int mt = 0; mt < 4; ++mt) {
                const int r0i = m0 + wm * 64 + mt * 16 + (lane >> 2);
                uint32_t h0, l0, h1, l1;
                split2(acc[mt][nt][0] + bx, h0, l0);
                split2(acc[mt][nt][1] + by, h1, l1);
                *(uint2*)&Yh[(size_t)r0i * E_DIM + col] = make_uint2(h0, h1);
                *(uint2*)&Yl[(size_t)r0i * E_DIM + col] = make_uint2(l0, l1);
                split2(acc[mt][nt][2] + bx, h0, l0);
                split2(acc[mt][nt][3] + by, h1, l1);
                *(uint2*)&Yh[(size_t)(r0i + 8) * E_DIM + col] = make_uint2(h0, h1);
                *(uint2*)&Yl[(size_t)(r0i + 8) * E_DIM + col] = make_uint2(l0, l1);
            }
        }
    }
}

// ===================== Tensorized causal flash attention (pre-split operands) =====================
// CTA: 64 q-rows x (b,h); 8 warps. Warp w: rows rg=w&3 (16), cols cn=w>>2 (32 of 64).
// Softmax partials exchanged within the warp pair via 1KB smem + named barrier.
// smem: Qhi|Qlo (32K) | 2 stages x {Khi,Klo,VThi,VTlo} (128K) | Phi|Plo (32K) | red (1K)
#define AQH   0u
#define AQL   16384u
#define ASTG  32768u
#define KHI   0u
#define KLO   16384u
#define VHI   32768u
#define VLO   49152u
#define ASTB  65536u
#define APH   163840u
#define APL   180224u
#define ARED  196608u
#define ATTN_SMEM 197632

__global__ __launch_bounds__(256) void attn_tc_kernel(void)
{
    extern __shared__ char smem[];
    const uint32_t sb = smem_u32(smem);
    float* red_m = (float*)(smem + ARED);          // [2][64]
    float* red_l = (float*)(smem + ARED + 512);    // [2][64]

    const int tid = threadIdx.x, lane = tid & 31, w = tid >> 5;
    const int rg = w & 3, cn = w >> 2;
    const int i = blockIdx.x, bh = blockIdx.y;
    const int b = bh >> 4, h = bh & 15;

    const size_t qbase  = ((size_t)b * S_LEN + i * 64) * E_DIM + h * 64;
    const size_t kbase  = (size_t)b * S_LEN * E_DIM + h * 64;
    const size_t vtbase = (size_t)bh * 64 * S_LEN;

    // Q hi/lo (once)
#pragma unroll
    for (int l = 0; l < 4; ++l) {
        int idx = tid + l * 256, row = idx >> 4, sl = idx & 15;
        uint32_t sw = (uint32_t)(row * 256 + ((sl ^ (row & 7)) << 4));
        size_t src = qbase + (size_t)row * E_DIM + sl * 4;
        CP16(sb + AQH + sw, s_q_hi + src);
        CP16(sb + AQL + sw, s_q_lo + src);
    }

    #define ISSUE_KV(j_, st_) do {                                             \
        uint32_t stb_ = sb + ASTG + (uint32_t)(st_) * ASTB;                    \
        _Pragma("unroll")                                                      \
        for (int l = 0; l < 4; ++l) {                                          \
            int idx_ = tid + l * 256, row_ = idx_ >> 4, sl_ = idx_ & 15;       \
            uint32_t sw_ = (uint32_t)(row_ * 256 + ((sl_ ^ (row_ & 7)) << 4)); \
            size_t ks_ = kbase + (size_t)((j_) * 64 + row_) * E_DIM + sl_ * 4; \
            size_t vs_ = vtbase + (size_t)row_ * S_LEN + (j_) * 64 + sl_ * 4;  \
            CP16(stb_ + KHI + sw_, s_k_hi + ks_);                              \
            CP16(stb_ + KLO + sw_, s_k_lo + ks_);                              \
            CP16(stb_ + VHI + sw_, s_vt_hi + vs_);                             \
            CP16(stb_ + VLO + sw_, s_vt_lo + vs_);                             \
        }                                                                      \
    } while (0)

    ISSUE_KV(0, 0);
    CPCOMMIT();

    const int i4 = lane >> 3, r8 = lane & 7;
    const int lr = lane >> 2;
    const int lc0 = 2 * (lane & 3);
    const int qrow = rg * 16 + ((i4 & 1) << 3) + r8;
    const int qrm = qrow & 7;
    const uint32_t qhb = sb + AQH + qrow * 256;
    const uint32_t qlb = sb + AQL + qrow * 256;
    const int prow = ((i4 & 1) << 3) + r8;
    const int prm = prow & 7;
    const uint32_t phb = sb + APH + (uint32_t)rg * 4096 + prow * 256;
    const uint32_t plb = sb + APL + (uint32_t)rg * 4096 + prow * 256;
    const uint32_t pwh = sb + APH + (uint32_t)rg * 4096;
    const uint32_t pwl = sb + APL + (uint32_t)rg * 4096;
    const int lrow0 = rg * 16 + lr;
    const int barid = rg + 1;
    const int rowA = rg * 16 + lr, rowB = rowA + 8;

    float m_prev0 = -INFINITY, m_prev1 = -INFINITY;
    float lsum0 = 0.f, lsum1 = 0.f;
    float o[4][4];
#pragma unroll
    for (int nt = 0; nt < 4; ++nt)
#pragma unroll
        for (int r = 0; r < 4; ++r) o[nt][r] = 0.f;

    for (int j = 0; j <= i; ++j) {
        CPWAIT0();
        __syncthreads();
        if (j < i) ISSUE_KV(j + 1, (j + 1) & 1);
        CPCOMMIT();

        const uint32_t stg = sb + ASTG + (uint32_t)(j & 1) * ASTB;

        // ---- S = Q K^T ----
        float sacc[4][4];
#pragma unroll
        for (int nt = 0; nt < 4; ++nt)
#pragma unroll
            for (int r = 0; r < 4; ++r) sacc[nt][r] = 0.f;

#pragma unroll
        for (int ks = 0; ks < 8; ++ks) {
            const uint32_t aoff = (uint32_t)((((ks << 1) | (i4 >> 1)) ^ qrm) << 4);
            uint32_t ah[4], al[4];
            LDSM_X4(ah[0], ah[1], ah[2], ah[3], qhb + aoff);
            LDSM_X4(al[0], al[1], al[2], al[3], qlb + aoff);
#pragma unroll
            for (int nt = 0; nt < 4; ++nt) {
                const int brow = cn * 32 + (nt << 3) + r8;
                const uint32_t boff = (uint32_t)(brow * 256
                    + ((((ks << 1) | (i4 & 1)) ^ (brow & 7)) << 4));
                uint32_t bh0, bh1, bl0, bl1;
                LDSM_X2(bh0, bh1, stg + KHI + boff);
                LDSM_X2(bl0, bl1, stg + KLO + boff);
                MMA_TF32(sacc[nt], ah, bl0, bl1);
                MMA_TF32(sacc[nt], al, bh0, bh1);
                MMA_TF32(sacc[nt], ah, bh0, bh1);
            }
        }

        // ---- softmax (pair-shared rows) ----
        const bool diag = (j == i);
        float mloc0 = -INFINITY, mloc1 = -INFINITY;
#pragma unroll
        for (int nt = 0; nt < 4; ++nt) {
            const int c0 = cn * 32 + (nt << 3) + lc0;
            float s0 = sacc[nt][0] * 0.125f, s1 = sacc[nt][1] * 0.125f;
            float s2 = sacc[nt][2] * 0.125f, s3 = sacc[nt][3] * 0.125f;
            if (diag) {
                if (c0     > lrow0)     s0 = -INFINITY;
                if (c0 + 1 > lrow0)     s1 = -INFINITY;
                if (c0     > lrow0 + 8) s2 = -INFINITY;
                if (c0 + 1 > lrow0 + 8) s3 = -INFINITY;
            }
            sacc[nt][0] = s0; sacc[nt][1] = s1; sacc[nt][2] = s2; sacc[nt][3] = s3;
            mloc0 = fmaxf(mloc0, fmaxf(s0, s1));
            mloc1 = fmaxf(mloc1, fmaxf(s2, s3));
        }
        mloc0 = fmaxf(mloc0, __shfl_xor_sync(0xffffffffu, mloc0, 1));
        mloc0 = fmaxf(mloc0, __shfl_xor_sync(0xffffffffu, mloc0, 2));
        mloc1 = fmaxf(mloc1, __shfl_xor_sync(0xffffffffu, mloc1, 1));
        mloc1 = fmaxf(mloc1, __shfl_xor_sync(0xffffffffu, mloc1, 2));

        if ((lane & 3) == 0) {
            red_m[cn * 64 + rowA] = mloc0;
            red_m[cn * 64 + rowB] = mloc1;
        }
        BARP(barid);
        const float m_new0 = fmaxf(m_prev0, fmaxf(mloc0, red_m[(cn ^ 1) * 64 + rowA]));
        const float m_new1 = fmaxf(m_prev1, fmaxf(mloc1, red_m[(cn ^ 1) * 64 + rowB]));
        const float fac0 = (m_prev0 == -INFINITY) ? 0.f : __expf(m_prev0 - m_new0);
        const float fac1 = (m_prev1 == -INFINITY) ? 0.f : __expf(m_prev1 - m_new1);
        m_prev0 = m_new0; m_prev1 = m_new1;

        float ls0 = 0.f, ls1 = 0.f;
        const int pslot_lo = (lane & 3) >> 1;
        const uint32_t pword = (uint32_t)((lane & 1) << 3);
#pragma unroll
        for (int nt = 0; nt < 4; ++nt) {
            float p0 = __expf(sacc[nt][0] - m_new0);
            float p1 = __expf(sacc[nt][1] - m_new0);
            float p2 = __expf(sacc[nt][2] - m_new1);
            float p3 = __expf(sacc[nt][3] - m_new1);
            ls0 += p0 + p1;
            ls1 += p2 + p3;
            const uint32_t slot = (uint32_t)((cn << 3) | (nt << 1) | pslot_lo);
            uint32_t h0, l0, h1, l1;
            split2(p0, h0, l0); split2(p1, h1, l1);
            STS64(pwh + lr * 256 + ((slot ^ (lr & 7)) << 4) + pword,
                  __uint_as_float(h0), __uint_as_float(h1));
            STS64(pwl + lr * 256 + ((slot ^ (lr & 7)) << 4) + pword,
                  __uint_as_float(l0), __uint_as_float(l1));
            split2(p2, h0, l0); split2(p3, h1, l1);
            STS64(pwh + (lr + 8) * 256 + ((slot ^ ((lr + 8) & 7)) << 4) + pword,
                  __uint_as_float(h0), __uint_as_float(h1));
            STS64(pwl + (lr + 8) * 256 + ((slot ^ ((lr + 8) & 7)) << 4) + pword,
                  __uint_as_float(l0), __uint_as_float(l1));
        }
        ls0 += __shfl_xor_sync(0xffffffffu, ls0, 1);
        ls0 += __shfl_xor_sync(0xffffffffu, ls0, 2);
        ls1 += __shfl_xor_sync(0xffffffffu, ls1, 1);
        ls1 += __shfl_xor_sync(0xffffffffu, ls1, 2);
        if ((lane & 3) == 0) {
            red_l[cn * 64 + rowA] = ls0;
            red_l[cn * 64 + rowB] = ls1;
        }
        BARP(barid);
        lsum0 = lsum0 * fac0 + red_l[rowA] + red_l[64 + rowA];
        lsum1 = lsum1 * fac1 + red_l[rowB] + red_l[64 + rowB];

#pragma unroll
        for (int nt = 0; nt < 4; ++nt) {
            o[nt][0] *= fac0; o[nt][1] *= fac0;
            o[nt][2] *= fac1; o[nt][3] *= fac1;
        }

        // ---- O += P V ----
#pragma unroll
        for (int ks = 0; ks < 8; ++ks) {
            const uint32_t aoff = (uint32_t)((((ks << 1) | (i4 >> 1)) ^ prm) << 4);
            uint32_t ah[4], al[4];
            LDSM_X4(ah[0], ah[1], ah[2], ah[3], phb + aoff);
            LDSM_X4(al[0], al[1], al[2], al[3], plb + aoff);
#pragma unroll
            for (int nt = 0; nt < 4; ++nt) {
                const int vrow = cn * 32 + (nt << 3) + r8;
                const uint32_t boff = (uint32_t)(vrow * 256
                    + ((((ks << 1) | (i4 & 1)) ^ (vrow & 7)) << 4));
                uint32_t bh0, bh1, bl0, bl1;
                LDSM_X2(bh0, bh1, stg + VHI + boff);
                LDSM_X2(bl0, bl1, stg + VLO + boff);
                MMA_TF32(o[nt], ah, bl0, bl1);
                MMA_TF32(o[nt], al, bh0, bh1);
                MMA_TF32(o[nt], ah, bh0, bh1);
            }
        }
    }

    // ---- epilogue: split O for the out-projection ----
    const float inv0 = 1.f / lsum0;
    const float inv1 = 1.f / lsum1;
    const size_t orowA = ((size_t)b * S_LEN + i * 64 + rg * 16 + lr) * E_DIM;
    const size_t orowB = orowA + (size_t)8 * E_DIM;
#pragma unroll
    for (int nt = 0; nt < 4; ++nt) {
        const int col = h * 64 + cn * 32 + (nt << 3) + lc0;
        uint32_t h0, l0, h1, l1;
        split2(o[nt][0] * inv0, h0, l0);
        split2(o[nt][1] * inv0, h1, l1);
        *(uint2*)&s_o_hi[orowA + col] = make_uint2(h0, h1);
        *(uint2*)&s_o_lo[orowA + col] = make_uint2(l0, l1);
        split2(o[nt][2] * inv1, h0, l0);
        split2(o[nt][3] * inv1, h1, l1);
        *(uint2*)&s_o_hi[orowB + col] = make_uint2(h0, h1);
        *(uint2*)&s_o_lo[orowB + col] = make_uint2(l0, l1);
    }
}

// ===================== launch =====================
extern "C" void kernel_launch(void* const* d_in, const int* in_sizes, int n_in,
                              void* d_out, int out_size)
{
    (void)in_sizes; (void)n_in; (void)out_size;
    const float* q  = (const float*)d_in[0];
    const float* k  = (const float*)d_in[1];
    const float* v  = (const float*)d_in[2];
    const float* Wq = (const float*)d_in[3];
    const float* bq = (const float*)d_in[4];
    const float* Wk = (const float*)d_in[5];
    const float* bk = (const float*)d_in[6];
    const float* Wv = (const float*)d_in[7];
    const float* bv = (const float*)d_in[8];
    const float* Wo = (const float*)d_in[9];
    const float* bo = (const float*)d_in[10];
    float* out = (float*)d_out;

    uint32_t *p_xq_hi, *p_xq_lo, *p_xk_hi, *p_xk_lo, *p_xv_hi, *p_xv_lo;
    uint32_t *p_wq_hi, *p_wq_lo, *p_wk_hi, *p_wk_lo, *p_wv_hi, *p_wv_lo, *p_wo_hi, *p_wo_lo;
    cudaGetSymbolAddress((void**)&p_xq_hi, s_xq_hi); cudaGetSymbolAddress((void**)&p_xq_lo, s_xq_lo);
    cudaGetSymbolAddress((void**)&p_xk_hi, s_xk_hi); cudaGetSymbolAddress((void**)&p_xk_lo, s_xk_lo);
    cudaGetSymbolAddress((void**)&p_xv_hi, s_xv_hi); cudaGetSymbolAddress((void**)&p_xv_lo, s_xv_lo);
    cudaGetSymbolAddress((void**)&p_wq_hi, s_wq_hi); cudaGetSymbolAddress((void**)&p_wq_lo, s_wq_lo);
    cudaGetSymbolAddress((void**)&p_wk_hi, s_wk_hi); cudaGetSymbolAddress((void**)&p_wk_lo, s_wk_lo);
    cudaGetSymbolAddress((void**)&p_wv_hi, s_wv_hi); cudaGetSymbolAddress((void**)&p_wv_lo, s_wv_lo);
    cudaGetSymbolAddress((void**)&p_wo_hi, s_wo_hi); cudaGetSymbolAddress((void**)&p_wo_lo, s_wo_lo);

    cudaFuncSetAttribute(gemm_tc_kernel, cudaFuncAttributeMaxDynamicSharedMemorySize, GEMM_SMEM);
    cudaFuncSetAttribute(attn_tc_kernel, cudaFuncAttributeMaxDynamicSharedMemorySize, ATTN_SMEM);

    // pre-split inputs and weights
    const int n4_me = (int)(ME / 4), n4_ee = (int)(EE / 4);
    split_kernel<<<n4_me / 256, 256>>>((const float4*)q,  (uint4*)p_xq_hi, (uint4*)p_xq_lo, n4_me);
    split_kernel<<<n4_me / 256, 256>>>((const float4*)k,  (uint4*)p_xk_hi, (uint4*)p_xk_lo, n4_me);
    split_kernel<<<n4_me / 256, 256>>>((const float4*)v,  (uint4*)p_xv_hi, (uint4*)p_xv_lo, n4_me);
    split_kernel<<<n4_ee / 256, 256>>>((const float4*)Wq, (uint4*)p_wq_hi, (uint4*)p_wq_lo, n4_ee);
    split_kernel<<<n4_ee / 256, 256>>>((const float4*)Wk, (uint4*)p_wk_hi, (uint4*)p_wk_lo, n4_ee);
    split_kernel<<<n4_ee / 256, 256>>>((const float4*)Wv, (uint4*)p_wv_hi, (uint4*)p_wv_lo, n4_ee);
    split_kernel<<<n4_ee / 256, 256>>>((const float4*)Wo, (uint4*)p_wo_hi, (uint4*)p_wo_lo, n4_ee);

    // Q/K/V projections (epilogues emit split attention operands)
    dim3 gridP(E_DIM / 128, M_ROWS / 128, 3);
    gemm_tc_kernel<<<gridP, 256, GEMM_SMEM>>>(bq, bk, bv, bo, out, 0);

    // causal flash attention (emits split O)
    dim3 gridA(S_LEN / 64, N_BATCH * N_HEADS);
    attn_tc_kernel<<<gridA, 256, ATTN_SMEM>>>();

    // output projection
    dim3 gridO(E_DIM / 128, M_ROWS / 128, 1);
    gemm_tc_kernel<<<gridO, 256, GEMM_SMEM>>>(bq, bk, bv, bo, out, 1);
}